// round 1
// baseline (speedup 1.0000x reference)
#include <cuda_runtime.h>
#include <float.h>
#include <math.h>

// Problem constants (fixed by setup_inputs)
#define NPTS 8192
#define KNN 16
#define GS 64
#define NCELLS (GS * GS)

// ---------------- scratch (static device globals; no dynamic allocation) ----
__device__ float    g_mx[NPTS], g_my[NPTS];      // ch2m coordinates (SoA)
__device__ unsigned g_bbox[4];                   // order-encoded minx,maxx,miny,maxy
__device__ int      g_counts[NCELLS];
__device__ int      g_start[NCELLS + 1];
__device__ int      g_fill[NCELLS];
__device__ int      g_cellof[NPTS];
__device__ float    g_bx[NPTS], g_by[NPTS];      // binned coords
__device__ int      g_bid[NPTS];                 // binned original ids
__device__ int      g_knn[NPTS * KNN];           // idx[j][k] = k-th nearest ch2m id
__device__ float    g_partial[32];

// Order-preserving float <-> unsigned encoding (for atomicMin/Max)
__device__ __forceinline__ unsigned encf(float f) {
    unsigned u = __float_as_uint(f);
    return (u & 0x80000000u) ? ~u : (u | 0x80000000u);
}
__device__ __forceinline__ float decf(unsigned u) {
    unsigned v = (u & 0x80000000u) ? (u ^ 0x80000000u) : ~u;
    return __uint_as_float(v);
}

// ---------------- kernels --------------------------------------------------

__global__ void k_init() {
    int t = blockIdx.x * blockDim.x + threadIdx.x;
    if (t < NCELLS) g_counts[t] = 0;
    if (t == 0) {
        g_bbox[0] = 0xFFFFFFFFu;  // min x
        g_bbox[1] = 0u;           // max x
        g_bbox[2] = 0xFFFFFFFFu;  // min y
        g_bbox[3] = 0u;           // max y
    }
}

// ch2m = polynomial(ch2, M1, M2); also accumulate bounding box of ch2m.
__global__ void k_poly(const float* __restrict__ ch2,
                       const float* __restrict__ M1,
                       const float* __restrict__ M2) {
    int i = blockIdx.x * blockDim.x + threadIdx.x;
    if (i >= NPTS) return;
    float x1 = ch2[2 * i], x2 = ch2[2 * i + 1];
    // B = [1,x1] outer [1,x2];  y = sum(B * M)
    float y1 = M1[0] + M1[1] * x2 + M1[2] * x1 + M1[3] * x1 * x2;
    float y2 = M2[0] + M2[1] * x2 + M2[2] * x1 + M2[3] * x1 * x2;
    g_mx[i] = y1;
    g_my[i] = y2;
    unsigned ex = encf(y1), ey = encf(y2);
    atomicMin(&g_bbox[0], ex);
    atomicMax(&g_bbox[1], ex);
    atomicMin(&g_bbox[2], ey);
    atomicMax(&g_bbox[3], ey);
}

__global__ void k_bin() {
    int i = blockIdx.x * blockDim.x + threadIdx.x;
    if (i >= NPTS) return;
    float minx = decf(g_bbox[0]), maxx = decf(g_bbox[1]);
    float miny = decf(g_bbox[2]), maxy = decf(g_bbox[3]);
    float ivx = (float)GS / fmaxf(maxx - minx, 1e-20f);
    float ivy = (float)GS / fmaxf(maxy - miny, 1e-20f);
    int cx = min(GS - 1, max(0, (int)((g_mx[i] - minx) * ivx)));
    int cy = min(GS - 1, max(0, (int)((g_my[i] - miny) * ivy)));
    int c = cy * GS + cx;
    g_cellof[i] = c;
    atomicAdd(&g_counts[c], 1);
}

// Exclusive prefix sum over NCELLS=4096 counts. One block, 1024 threads x 4.
__global__ void k_scan() {
    __shared__ int tsum[1024];
    int t = threadIdx.x;
    int v0 = g_counts[4 * t + 0];
    int v1 = g_counts[4 * t + 1];
    int v2 = g_counts[4 * t + 2];
    int v3 = g_counts[4 * t + 3];
    int s1 = v0, s2 = v0 + v1, s3 = s2 + v2, s4 = s3 + v3;
    tsum[t] = s4;
    __syncthreads();
    for (int o = 1; o < 1024; o <<= 1) {
        int u = (t >= o) ? tsum[t - o] : 0;
        __syncthreads();
        tsum[t] += u;
        __syncthreads();
    }
    int excl = tsum[t] - s4;
    g_start[4 * t + 0] = excl;
    g_start[4 * t + 1] = excl + s1;
    g_start[4 * t + 2] = excl + s2;
    g_start[4 * t + 3] = excl + s3;
    g_fill[4 * t + 0] = excl;
    g_fill[4 * t + 1] = excl + s1;
    g_fill[4 * t + 2] = excl + s2;
    g_fill[4 * t + 3] = excl + s3;
    if (t == 1023) g_start[NCELLS] = tsum[1023];
}

__global__ void k_scatter() {
    int i = blockIdx.x * blockDim.x + threadIdx.x;
    if (i >= NPTS) return;
    int c = g_cellof[i];
    int p = atomicAdd(&g_fill[c], 1);
    g_bx[p] = g_mx[i];
    g_by[p] = g_my[i];
    g_bid[p] = i;
}

// Scan one cell's candidates, maintain sorted ascending top-16 in registers.
#define SCAN_CELL(CX, CY)                                                     \
    do {                                                                      \
        int c_ = (CY) * GS + (CX);                                            \
        int e_ = g_start[c_ + 1];                                             \
        for (int t_ = g_start[c_]; t_ < e_; ++t_) {                           \
            float dx_ = qx - g_bx[t_];                                        \
            float dy_ = qy - g_by[t_];                                        \
            float d_ = __fadd_rn(__fmul_rn(dx_, dx_), __fmul_rn(dy_, dy_));   \
            if (d_ < bd[KNN - 1]) {                                           \
                bd[KNN - 1] = d_;                                             \
                bi[KNN - 1] = g_bid[t_];                                      \
                _Pragma("unroll")                                             \
                for (int s_ = KNN - 1; s_ > 0; --s_) {                        \
                    if (bd[s_] < bd[s_ - 1]) {                                \
                        float td_ = bd[s_]; bd[s_] = bd[s_ - 1]; bd[s_ - 1] = td_; \
                        int ti_ = bi[s_]; bi[s_] = bi[s_ - 1]; bi[s_ - 1] = ti_;   \
                    }                                                         \
                }                                                             \
            }                                                                 \
        }                                                                     \
    } while (0)

// For each ch1 point: exact 16-NN over ch2m via expanding Chebyshev rings.
__global__ void k_query(const float* __restrict__ ch1) {
    int j = blockIdx.x * blockDim.x + threadIdx.x;
    if (j >= NPTS) return;
    float qx = ch1[2 * j], qy = ch1[2 * j + 1];

    float minx = decf(g_bbox[0]), maxx = decf(g_bbox[1]);
    float miny = decf(g_bbox[2]), maxy = decf(g_bbox[3]);
    float rxr = fmaxf(maxx - minx, 1e-20f);
    float ryr = fmaxf(maxy - miny, 1e-20f);
    float ivx = (float)GS / rxr, ivy = (float)GS / ryr;
    float hx = rxr / (float)GS, hy = ryr / (float)GS;
    int qcx = min(GS - 1, max(0, (int)((qx - minx) * ivx)));
    int qcy = min(GS - 1, max(0, (int)((qy - miny) * ivy)));

    float bd[KNN];
    int bi[KNN];
#pragma unroll
    for (int s = 0; s < KNN; s++) { bd[s] = FLT_MAX; bi[s] = 0; }

    for (int r = 0; r <= GS; ++r) {
        if (r > 0 && bd[KNN - 1] < FLT_MAX) {
            // Lower bound on distance from q to any cell of Chebyshev ring r.
            float b = FLT_MAX;
            if (qcx - r >= 0) b = fminf(b, qx - (minx + (float)(qcx - r + 1) * hx));
            if (qcx + r < GS) b = fminf(b, (minx + (float)(qcx + r) * hx) - qx);
            if (qcy - r >= 0) b = fminf(b, qy - (miny + (float)(qcy - r + 1) * hy));
            if (qcy + r < GS) b = fminf(b, (miny + (float)(qcy + r) * hy) - qy);
            if (b == FLT_MAX) break;            // ring entirely off-grid -> done
            b = fmaxf(b - 1e-4f, 0.0f);         // slack for binning rounding
            if (b * b > bd[KNN - 1]) break;     // no closer point can exist
        }
        if (r == 0) {
            SCAN_CELL(qcx, qcy);
        } else {
            int x0 = max(0, qcx - r), x1 = min(GS - 1, qcx + r);
            if (qcy - r >= 0) for (int cx = x0; cx <= x1; ++cx) SCAN_CELL(cx, qcy - r);
            if (qcy + r < GS) for (int cx = x0; cx <= x1; ++cx) SCAN_CELL(cx, qcy + r);
            int y0 = max(0, qcy - r + 1), y1 = min(GS - 1, qcy + r - 1);
            if (qcx - r >= 0) for (int cy = y0; cy <= y1; ++cy) SCAN_CELL(qcx - r, cy);
            if (qcx + r < GS) for (int cy = y0; cy <= y1; ++cy) SCAN_CELL(qcx + r, cy);
        }
    }

#pragma unroll
    for (int s = 0; s < KNN; s++) g_knn[j * KNN + s] = bi[s];
}

// Scrambled gather + KL log-sum. knn[k',n'] uses idx[k'*512 + n'/16][n'%16],
// distance evaluated against ch1[n'].
__global__ void k_gather(const float* __restrict__ ch1) {
    int n = blockIdx.x * blockDim.x + threadIdx.x;
    float contrib = 0.0f;
    if (n < NPTS) {
        float qx = ch1[2 * n], qy = ch1[2 * n + 1];
        int q = n >> 4, col = n & 15;
        const float inv_s4 = 1.0f / 2.25f;  // 1 / sigma2^2, sigma2 = 1.5
        float acc = 0.0f;
#pragma unroll
        for (int k = 0; k < 16; k++) {
            int sel = g_knn[(k * 512 + q) * KNN + col];
            float dx = qx - g_mx[sel];
            float dy = qy - g_my[sel];
            float D = 0.5f * (__fmul_rn(dx, dx) * inv_s4 + __fmul_rn(dy, dy) * inv_s4);
            acc += expf(-D);
        }
        float expD = acc * (1.0f / (float)NPTS);
        contrib = (expD != 0.0f) ? logf(expD) : 0.0f;
    }
    __shared__ float sm[256];
    sm[threadIdx.x] = contrib;
    __syncthreads();
    for (int o = 128; o > 0; o >>= 1) {
        if (threadIdx.x < o) sm[threadIdx.x] += sm[threadIdx.x + o];
        __syncthreads();
    }
    if (threadIdx.x == 0) g_partial[blockIdx.x] = sm[0];
}

__global__ void k_final(float* __restrict__ out) {
    float v = (threadIdx.x < 32) ? g_partial[threadIdx.x] : 0.0f;
    for (int o = 16; o > 0; o >>= 1) v += __shfl_down_sync(0xFFFFFFFFu, v, o);
    if (threadIdx.x == 0) out[0] = -v;
}

// ---------------- launch ----------------------------------------------------

extern "C" void kernel_launch(void* const* d_in, const int* in_sizes, int n_in,
                              void* d_out, int out_size) {
    (void)in_sizes; (void)n_in; (void)out_size;
    const float* ch1 = (const float*)d_in[0];
    const float* ch2 = (const float*)d_in[1];
    const float* M1  = (const float*)d_in[2];
    const float* M2  = (const float*)d_in[3];
    float* out = (float*)d_out;

    k_init<<<16, 256>>>();
    k_poly<<<32, 256>>>(ch2, M1, M2);
    k_bin<<<32, 256>>>();
    k_scan<<<1, 1024>>>();
    k_scatter<<<32, 256>>>();
    k_query<<<128, 64>>>(ch1);
    k_gather<<<32, 256>>>(ch1);
    k_final<<<1, 32>>>(out);
}